// round 1
// baseline (speedup 1.0000x reference)
#include <cuda_runtime.h>
#include <math.h>

#define C 64
#define P (512 * 512)          // 262144 pixels
#define K 20
#define NUM_CLASSES 11
#define EPS 1e-8f

#define NBLOCK 512
#define PIX_PER_BLOCK (P / NBLOCK)   // 512
#define TILE 64
#define NTILE (PIX_PER_BLOCK / TILE) // 8

// Per-block partials: sum1[20][64] | usum[20][64] | counts[20] | sq[20]  = 2600 floats
#define PART_STRIDE 2600
#define OFF_SUM1 0
#define OFF_USUM 1280
#define OFF_CNT 2560
#define OFF_SQ 2580

static __device__ float g_part[NBLOCK * PART_STRIDE];

// ---------------------------------------------------------------------------
// Main pass: per-block partial sums over its pixel chunk.
// Threads: 256 = 64 channels (c = tid & 63) x 4 k-groups (kg = tid >> 6).
// Each thread accumulates k = kg + 4j, j = 0..4 (covers k = 0..19).
// ---------------------------------------------------------------------------
__global__ void __launch_bounds__(256, 4)
main_pass(const float* __restrict__ v1g,
          const float* __restrict__ v2g,
          const int* __restrict__ masks)
{
    __shared__ float s_v1[C * 65];
    __shared__ float s_v2[C * 65];
    __shared__ float s_s1[TILE];   // per-pixel sum of v1^2 over channels
    __shared__ float s_inv[TILE];  // per-pixel 1/max(||v2||, eps)
    __shared__ int   s_mb[TILE];   // per-pixel 20-bit mask word

    const int tid = threadIdx.x;
    const int c   = tid & 63;
    const int kg  = tid >> 6;      // 0..3

    int bitm[5];
#pragma unroll
    for (int j = 0; j < 5; ++j) bitm[j] = 1 << (kg + 4 * j);

    float acc1[5] = {0.f, 0.f, 0.f, 0.f, 0.f};
    float acc2[5] = {0.f, 0.f, 0.f, 0.f, 0.f};
    float cntAcc = 0.f;   // only meaningful for tid < 20
    float sqAcc  = 0.f;

    const int p0_blk = blockIdx.x * PIX_PER_BLOCK;

    for (int t = 0; t < NTILE; ++t) {
        const int p0 = p0_blk + t * TILE;
        __syncthreads();   // smem reuse barrier (prev tile's readers done)

        // ---- Phase A: stage tiles (coalesced) -----------------------------
#pragma unroll
        for (int i = 0; i < (C * TILE) / 256; ++i) {      // 16 iters
            int idx = tid + i * 256;
            int cc = idx >> 6;
            int pp = idx & 63;
            s_v1[cc * 65 + pp] = v1g[(size_t)cc * P + p0 + pp];
            s_v2[cc * 65 + pp] = v2g[(size_t)cc * P + p0 + pp];
        }
        if (tid < TILE) {
            int mb = 0;
#pragma unroll
            for (int k = 0; k < K; ++k) {
                int m = masks[(size_t)k * P + p0 + tid];
                mb |= (m & 1) << k;
            }
            s_mb[tid] = mb;
        }
        __syncthreads();

        // ---- Phase B: per-pixel norms (tid < 64, conflict-free LDS) -------
        if (tid < TILE) {
            const int p = tid;
            float s1 = 0.f, s2 = 0.f;
#pragma unroll 8
            for (int cc = 0; cc < C; ++cc) {
                float a = s_v1[cc * 65 + p];
                float b = s_v2[cc * 65 + p];
                s1 = fmaf(a, a, s1);
                s2 = fmaf(b, b, s2);
            }
            s_s1[p]  = s1;
            s_inv[p] = 1.0f / fmaxf(sqrtf(s2), EPS);
        }
        __syncthreads();

        // ---- Phase C: masked accumulation ---------------------------------
#pragma unroll 4
        for (int p = 0; p < TILE; ++p) {
            int   mb  = s_mb[p];                 // broadcast
            float va  = s_v1[c * 65 + p];        // conflict-free (stride 65)
            float vb  = s_v2[c * 65 + p] * s_inv[p];
#pragma unroll
            for (int j = 0; j < 5; ++j) {
                if (mb & bitm[j]) { acc1[j] += va; acc2[j] += vb; }
            }
        }

        // counts + sq: 20 threads, one per instance
        if (tid < K) {
            const int k = tid;
            float c0 = 0.f, s0 = 0.f;
#pragma unroll 8
            for (int p = 0; p < TILE; ++p) {
                if ((s_mb[p] >> k) & 1) { c0 += 1.0f; s0 += s_s1[p]; }
            }
            cntAcc += c0;
            sqAcc  += s0;
        }
    }

    // ---- write per-block partials ----------------------------------------
    float* base = g_part + (size_t)blockIdx.x * PART_STRIDE;
#pragma unroll
    for (int j = 0; j < 5; ++j) {
        int k = kg + 4 * j;
        base[OFF_SUM1 + k * C + c] = acc1[j];
        base[OFF_USUM + k * C + c] = acc2[j];
    }
    if (tid < K) {
        base[OFF_CNT + tid] = cntAcc;
        base[OFF_SQ  + tid] = sqAcc;
    }
}

// ---------------------------------------------------------------------------
// Finalize: deterministic reduction of partials + all the small math.
// Single block, 512 threads.
// ---------------------------------------------------------------------------
__global__ void __launch_bounds__(512, 1)
finalize(const int* __restrict__ labels, float* __restrict__ out)
{
    __shared__ float S[PART_STRIDE];   // sum1 | usum | cnt | sq  (reduced)
    __shared__ float m1n[K * C];       // normalized mean1
    __shared__ float simm[K * K];
    __shared__ float stdv[K];

    const int tid = threadIdx.x;

    // fixed-order reduction over blocks (deterministic)
    for (int i = tid; i < PART_STRIDE; i += 512) {
        float s = 0.f;
        for (int b = 0; b < NBLOCK; ++b)
            s += g_part[(size_t)b * PART_STRIDE + i];
        S[i] = s;
    }
    __syncthreads();

    // per-instance stats
    if (tid < K) {
        const int k = tid;
        float cnt = S[OFF_CNT + k];
        float ssum = 0.f;
        for (int cc = 0; cc < C; ++cc) ssum += S[OFF_SUM1 + k * C + cc];
        float n_elem = cnt * (float)C;
        float em  = ssum / n_elem;
        float var = (S[OFF_SQ + k] - n_elem * em * em) / (n_elem - 1.0f);
        stdv[k] = sqrtf(fmaxf(var, 0.0f));

        float nrm2 = 0.f;
        for (int cc = 0; cc < C; ++cc) {
            float m = S[OFF_SUM1 + k * C + cc] / cnt;
            m1n[k * C + cc] = m;
            nrm2 = fmaf(m, m, nrm2);
        }
        float inv = 1.0f / fmaxf(sqrtf(nrm2), EPS);
        for (int cc = 0; cc < C; ++cc) m1n[k * C + cc] *= inv;
        // u = usum / cnt (overwrite in place)
        for (int cc = 0; cc < C; ++cc) S[OFF_USUM + k * C + cc] /= cnt;
    }
    __syncthreads();

    // sim[i][j] = mean1n[i] . u[j]
    if (tid < K * K) {
        int i = tid / K;
        int j = tid % K;
        float d = 0.f;
#pragma unroll 8
        for (int cc = 0; cc < C; ++cc)
            d = fmaf(m1n[i * C + cc], S[OFF_USUM + j * C + cc], d);
        simm[i * K + j] = d;
    }
    __syncthreads();

    if (tid == 0) {
        int cls[K];
        for (int i = 0; i < K; ++i) cls[i] = labels[i];

        float inst[NUM_CLASSES]  = {};
        float clsim[NUM_CLASSES] = {};
        float clstd[NUM_CLASSES] = {};
        float csum[NUM_CLASSES]  = {};
        float negsum = 0.f;
        int   negcnt = 0;

        for (int i = 0; i < K; ++i) {
            int ci = cls[i];
            inst[ci]  += simm[i * K + i];
            clstd[ci] += stdv[i];
            csum[ci]  += 1.0f;
            for (int j = 0; j < K; ++j) {
                if (j == i) continue;
                if (cls[j] == ci) clsim[ci] += simm[i * K + j];
                else { negsum += simm[i * K + j]; negcnt++; }
            }
        }
        for (int cc = 0; cc < NUM_CLASSES; ++cc) {
            if (csum[cc] > 1.0f) {
                inst[cc]  /= csum[cc];
                clsim[cc] /= csum[cc] * (csum[cc] - 1.0f);
                clstd[cc] /= csum[cc];
            }
        }
        for (int cc = 0; cc < NUM_CLASSES; ++cc) {
            out[cc]      = inst[cc];
            out[11 + cc] = clsim[cc];
            out[23 + cc] = clstd[cc];
        }
        out[22] = negsum / (float)negcnt;
    }
}

extern "C" void kernel_launch(void* const* d_in, const int* in_sizes, int n_in,
                              void* d_out, int out_size)
{
    const float* v1     = (const float*)d_in[0];
    const float* v2     = (const float*)d_in[1];
    const int*   labels = (const int*)d_in[2];
    const int*   masks  = (const int*)d_in[3];
    float* out = (float*)d_out;

    main_pass<<<NBLOCK, 256>>>(v1, v2, masks);
    finalize<<<1, 512>>>(labels, out);
}

// round 2
// speedup vs baseline: 1.3125x; 1.3125x over previous
#include <cuda_runtime.h>
#include <math.h>

#define C 64
#define P (512 * 512)          // 262144 pixels
#define K 20
#define NUM_CLASSES 11
#define EPS 1e-8f

#define NBLOCK 512
#define PIX_PER_BLOCK (P / NBLOCK)   // 512
#define TILE 64
#define NTILE (PIX_PER_BLOCK / TILE) // 8

// Per-block partials: sum1[20][64] | usum[20][64] | counts[20] | sq[20]  = 2600 floats
#define PART_STRIDE 2600
#define OFF_SUM1 0
#define OFF_USUM 1280
#define OFF_CNT 2560
#define OFF_SQ 2580

static __device__ float g_part[NBLOCK * PART_STRIDE];
static __device__ float g_red[PART_STRIDE];

// ---------------------------------------------------------------------------
// Main pass: per-block partial sums over its pixel chunk.
// Threads: 256 = 64 channels (c = tid & 63) x 4 k-groups (kg = tid >> 6).
// Each thread accumulates k = kg + 4j, j = 0..4 (covers k = 0..19).
// ---------------------------------------------------------------------------
__global__ void __launch_bounds__(256, 4)
main_pass(const float* __restrict__ v1g,
          const float* __restrict__ v2g,
          const int* __restrict__ masks)
{
    __shared__ float s_v1[C * 65];
    __shared__ float s_v2[C * 65];
    __shared__ float s_p1[4 * TILE];   // partial sums of v1^2 (4-way split)
    __shared__ float s_p2[4 * TILE];   // partial sums of v2^2
    __shared__ float s_s1[TILE];       // per-pixel sum of v1^2 over channels
    __shared__ float s_inv[TILE];      // per-pixel 1/max(||v2||, eps)
    __shared__ int   s_mb[TILE];       // per-pixel 20-bit mask word

    const int tid = threadIdx.x;
    const int c   = tid & 63;
    const int kg  = tid >> 6;      // 0..3
    const int p_l = tid & 63;      // pixel lane for phases B
    const int q_l = tid >> 6;      // channel quarter for phases B

    int bitm[5];
#pragma unroll
    for (int j = 0; j < 5; ++j) bitm[j] = 1 << (kg + 4 * j);

    float acc1[5] = {0.f, 0.f, 0.f, 0.f, 0.f};
    float acc2[5] = {0.f, 0.f, 0.f, 0.f, 0.f};
    float cntAcc = 0.f;   // only meaningful for tid < 20
    float sqAcc  = 0.f;

    const int p0_blk = blockIdx.x * PIX_PER_BLOCK;

    for (int t = 0; t < NTILE; ++t) {
        const int p0 = p0_blk + t * TILE;
        __syncthreads();   // smem reuse barrier (prev tile's readers done)

        // ---- Phase A: stage tiles (coalesced, vectorized) -----------------
        // 64x64 floats = 1024 float4 per array; 256 threads -> 4 iters each.
#pragma unroll
        for (int i = 0; i < 4; ++i) {
            int idx = tid + i * 256;          // float4 index
            int cc = idx >> 4;                // 16 float4 per row of 64
            int pp = (idx & 15) * 4;
            float4 a = *(const float4*)&v1g[(size_t)cc * P + p0 + pp];
            float4 b = *(const float4*)&v2g[(size_t)cc * P + p0 + pp];
            float* d1 = &s_v1[cc * 65 + pp];
            float* d2 = &s_v2[cc * 65 + pp];
            d1[0] = a.x; d1[1] = a.y; d1[2] = a.z; d1[3] = a.w;
            d2[0] = b.x; d2[1] = b.y; d2[2] = b.z; d2[3] = b.w;
        }
        if (tid < TILE) {
            int mb = 0;
#pragma unroll
            for (int k = 0; k < K; ++k) {
                int m = masks[(size_t)k * P + p0 + tid];
                mb |= (m & 1) << k;
            }
            s_mb[tid] = mb;
        }
        __syncthreads();

        // ---- Phase B1: per-pixel norm partials (all 256 threads) ----------
        {
            float s1 = 0.f, s2 = 0.f;
            const int cbase = q_l * 16;
#pragma unroll
            for (int cc = 0; cc < 16; ++cc) {
                float a = s_v1[(cbase + cc) * 65 + p_l];
                float b = s_v2[(cbase + cc) * 65 + p_l];
                s1 = fmaf(a, a, s1);
                s2 = fmaf(b, b, s2);
            }
            s_p1[q_l * TILE + p_l] = s1;
            s_p2[q_l * TILE + p_l] = s2;
        }
        __syncthreads();

        // ---- Phase B2: combine (64 threads) -------------------------------
        if (tid < TILE) {
            float s1 = s_p1[tid] + s_p1[TILE + tid] + s_p1[2 * TILE + tid] + s_p1[3 * TILE + tid];
            float s2 = s_p2[tid] + s_p2[TILE + tid] + s_p2[2 * TILE + tid] + s_p2[3 * TILE + tid];
            s_s1[tid]  = s1;
            s_inv[tid] = 1.0f / fmaxf(sqrtf(s2), EPS);
        }
        __syncthreads();

        // ---- Phase B3: scale v2 in place (all 256 threads) ----------------
        {
            float inv = s_inv[p_l];
            const int cbase = q_l * 16;
#pragma unroll
            for (int cc = 0; cc < 16; ++cc) {
                s_v2[(cbase + cc) * 65 + p_l] *= inv;
            }
        }
        __syncthreads();

        // ---- Phase C: masked accumulation ---------------------------------
#pragma unroll 4
        for (int p = 0; p < TILE; ++p) {
            int   mb  = s_mb[p];                 // warp-uniform broadcast
            float va  = s_v1[c * 65 + p];        // conflict-free (stride 65)
            float vb  = s_v2[c * 65 + p];
#pragma unroll
            for (int j = 0; j < 5; ++j) {
                if (mb & bitm[j]) { acc1[j] += va; acc2[j] += vb; }
            }
        }

        // counts + sq: 20 threads, one per instance
        if (tid < K) {
            const int k = tid;
            float c0 = 0.f, s0 = 0.f;
#pragma unroll 8
            for (int p = 0; p < TILE; ++p) {
                if ((s_mb[p] >> k) & 1) { c0 += 1.0f; s0 += s_s1[p]; }
            }
            cntAcc += c0;
            sqAcc  += s0;
        }
    }

    // ---- write per-block partials ----------------------------------------
    float* base = g_part + (size_t)blockIdx.x * PART_STRIDE;
#pragma unroll
    for (int j = 0; j < 5; ++j) {
        int k = kg + 4 * j;
        base[OFF_SUM1 + k * C + c] = acc1[j];
        base[OFF_USUM + k * C + c] = acc2[j];
    }
    if (tid < K) {
        base[OFF_CNT + tid] = cntAcc;
        base[OFF_SQ  + tid] = sqAcc;
    }
}

// ---------------------------------------------------------------------------
// Reduce: one warp per partial index i. Deterministic fixed-order sum:
// lane l sums blocks b = l + 32*j (j = 0..15) in order, then a fixed
// butterfly shuffle tree. High MLP across the whole chip.
// ---------------------------------------------------------------------------
#define RED_TPB 128
#define RED_WARPS (RED_TPB / 32)
#define RED_BLOCKS ((PART_STRIDE + RED_WARPS - 1) / RED_WARPS)   // 650

__global__ void __launch_bounds__(RED_TPB, 8)
reduce_partials()
{
    const int wid  = (blockIdx.x * RED_WARPS) + (threadIdx.x >> 5);
    const int lane = threadIdx.x & 31;
    if (wid >= PART_STRIDE) return;

    float s = 0.f;
#pragma unroll
    for (int j = 0; j < NBLOCK / 32; ++j) {         // 16
        int b = lane + 32 * j;
        s += g_part[(size_t)b * PART_STRIDE + wid];
    }
#pragma unroll
    for (int off = 16; off > 0; off >>= 1)
        s += __shfl_xor_sync(0xFFFFFFFFu, s, off);

    if (lane == 0) g_red[wid] = s;
}

// ---------------------------------------------------------------------------
// Finalize: small math on reduced sums. Single block, 512 threads.
// ---------------------------------------------------------------------------
__global__ void __launch_bounds__(512, 1)
finalize(const int* __restrict__ labels, float* __restrict__ out)
{
    __shared__ float S[PART_STRIDE];   // sum1 | usum | cnt | sq  (reduced)
    __shared__ float m1n[K * C];       // normalized mean1
    __shared__ float simm[K * K];
    __shared__ float stdv[K];

    const int tid = threadIdx.x;

    for (int i = tid; i < PART_STRIDE; i += 512) S[i] = g_red[i];
    __syncthreads();

    // per-instance stats
    if (tid < K) {
        const int k = tid;
        float cnt = S[OFF_CNT + k];
        float ssum = 0.f;
        for (int cc = 0; cc < C; ++cc) ssum += S[OFF_SUM1 + k * C + cc];
        float n_elem = cnt * (float)C;
        float em  = ssum / n_elem;
        float var = (S[OFF_SQ + k] - n_elem * em * em) / (n_elem - 1.0f);
        stdv[k] = sqrtf(fmaxf(var, 0.0f));

        float nrm2 = 0.f;
        for (int cc = 0; cc < C; ++cc) {
            float m = S[OFF_SUM1 + k * C + cc] / cnt;
            m1n[k * C + cc] = m;
            nrm2 = fmaf(m, m, nrm2);
        }
        float inv = 1.0f / fmaxf(sqrtf(nrm2), EPS);
        for (int cc = 0; cc < C; ++cc) m1n[k * C + cc] *= inv;
        // u = usum / cnt (overwrite in place)
        for (int cc = 0; cc < C; ++cc) S[OFF_USUM + k * C + cc] /= cnt;
    }
    __syncthreads();

    // sim[i][j] = mean1n[i] . u[j]
    if (tid < K * K) {
        int i = tid / K;
        int j = tid % K;
        float d = 0.f;
#pragma unroll 8
        for (int cc = 0; cc < C; ++cc)
            d = fmaf(m1n[i * C + cc], S[OFF_USUM + j * C + cc], d);
        simm[i * K + j] = d;
    }
    __syncthreads();

    if (tid == 0) {
        int cls[K];
        for (int i = 0; i < K; ++i) cls[i] = labels[i];

        float inst[NUM_CLASSES]  = {};
        float clsim[NUM_CLASSES] = {};
        float clstd[NUM_CLASSES] = {};
        float csum[NUM_CLASSES]  = {};
        float negsum = 0.f;
        int   negcnt = 0;

        for (int i = 0; i < K; ++i) {
            int ci = cls[i];
            inst[ci]  += simm[i * K + i];
            clstd[ci] += stdv[i];
            csum[ci]  += 1.0f;
            for (int j = 0; j < K; ++j) {
                if (j == i) continue;
                if (cls[j] == ci) clsim[ci] += simm[i * K + j];
                else { negsum += simm[i * K + j]; negcnt++; }
            }
        }
        for (int cc = 0; cc < NUM_CLASSES; ++cc) {
            if (csum[cc] > 1.0f) {
                inst[cc]  /= csum[cc];
                clsim[cc] /= csum[cc] * (csum[cc] - 1.0f);
                clstd[cc] /= csum[cc];
            }
        }
        for (int cc = 0; cc < NUM_CLASSES; ++cc) {
            out[cc]      = inst[cc];
            out[11 + cc] = clsim[cc];
            out[23 + cc] = clstd[cc];
        }
        out[22] = negsum / (float)negcnt;
    }
}

extern "C" void kernel_launch(void* const* d_in, const int* in_sizes, int n_in,
                              void* d_out, int out_size)
{
    const float* v1     = (const float*)d_in[0];
    const float* v2     = (const float*)d_in[1];
    const int*   labels = (const int*)d_in[2];
    const int*   masks  = (const int*)d_in[3];
    float* out = (float*)d_out;

    main_pass<<<NBLOCK, 256>>>(v1, v2, masks);
    reduce_partials<<<RED_BLOCKS, RED_TPB>>>();
    finalize<<<1, 512>>>(labels, out);
}